// round 14
// baseline (speedup 1.0000x reference)
#include <cuda_runtime.h>
#include <cuda_bf16.h>
#include <cstdint>
#include <float.h>
#include <math.h>

#define BB   64
#define NT   197
#define CT   768
#define HT   12
#define DT   64
#define LEFT 137
#define MROWS (BB*NT)     // 12608

// device scratch
__device__ uint32_t g_qh[BB*HT*NT*32];
__device__ uint32_t g_ql[BB*HT*NT*32];
__device__ uint32_t g_kh[BB*HT*NT*32];
__device__ uint32_t g_kl[BB*HT*NT*32];
__device__ float    g_v [BB*HT*NT*DT];
__device__ float    g_ao[BB*NT*CT];
__device__ float    g_wt[BB*HT*CT];
__device__ float    g_beta[BB*HT];
__device__ float    g_qc[BB*CT];
__device__ float    g_xr[MROWS*CT];
__device__ float    g_wqr[3*CT*CT];
__device__ float    g_wpr[CT*CT];

// ---------------------------------------------------------------------------
// helpers
// ---------------------------------------------------------------------------
__device__ __forceinline__ uint32_t smem_u32(const void* p) {
    uint32_t a;
    asm("{ .reg .u64 t; cvta.to.shared.u64 t, %1; cvt.u32.u64 %0, t; }" : "=r"(a) : "l"(p));
    return a;
}
__device__ __forceinline__ void cp16(uint32_t saddr, const void* g) {
    asm volatile("cp.async.ca.shared.global [%0], [%1], 16;" :: "r"(saddr), "l"(g));
}
__device__ __forceinline__ void cp_commit() {
    asm volatile("cp.async.commit_group;" ::: "memory");
}
__device__ __forceinline__ void cp_wait1() {
    asm volatile("cp.async.wait_group 1;" ::: "memory");
}
__device__ __forceinline__ void cp_wait0() {
    asm volatile("cp.async.wait_group 0;" ::: "memory");
}
__device__ __forceinline__ uint32_t f2tf32(float v) {
    uint32_t r;
    asm("cvt.rna.tf32.f32 %0, %1;" : "=r"(r) : "f"(v));
    return r;
}
__device__ __forceinline__ float roundtf(float v) {
    return __uint_as_float(f2tf32(v));
}
__device__ __forceinline__ uint32_t packbf(float x, float y) {
    __nv_bfloat162 t = __floats2bfloat162_rn(x, y);
    return *reinterpret_cast<uint32_t*>(&t);
}
__device__ __forceinline__ void bf16split(float x, float y, uint32_t& hi, uint32_t& lo) {
    float xh = __bfloat162float(__float2bfloat16_rn(x));
    float yh = __bfloat162float(__float2bfloat16_rn(y));
    hi = packbf(xh, yh);
    lo = packbf(x - xh, y - yh);
}
__device__ __forceinline__ void ldsm4(uint32_t& r0, uint32_t& r1, uint32_t& r2,
                                      uint32_t& r3, uint32_t sa) {
    asm volatile("ldmatrix.sync.aligned.m8n8.x4.shared.b16 {%0,%1,%2,%3}, [%4];"
                 : "=r"(r0), "=r"(r1), "=r"(r2), "=r"(r3) : "r"(sa));
}
__device__ __forceinline__ void ldsm2(uint32_t& r0, uint32_t& r1, uint32_t sa) {
    asm volatile("ldmatrix.sync.aligned.m8n8.x2.shared.b16 {%0,%1}, [%2];"
                 : "=r"(r0), "=r"(r1) : "r"(sa));
}
__device__ __forceinline__ void mma_tf32(float c[4], uint32_t a0, uint32_t a1,
                                         uint32_t a2, uint32_t a3,
                                         uint32_t b0, uint32_t b1) {
    asm volatile(
        "mma.sync.aligned.m16n8k8.row.col.f32.tf32.tf32.f32 "
        "{%0,%1,%2,%3}, {%4,%5,%6,%7}, {%8,%9}, {%0,%1,%2,%3};"
        : "+f"(c[0]), "+f"(c[1]), "+f"(c[2]), "+f"(c[3])
        : "r"(a0), "r"(a1), "r"(a2), "r"(a3), "r"(b0), "r"(b1));
}
__device__ __forceinline__ void mma_bf16(float c[4], uint32_t a0, uint32_t a1,
                                         uint32_t a2, uint32_t a3,
                                         uint32_t b0, uint32_t b1) {
    asm volatile(
        "mma.sync.aligned.m16n8k16.row.col.f32.bf16.bf16.f32 "
        "{%0,%1,%2,%3}, {%4,%5,%6,%7}, {%8,%9}, {%0,%1,%2,%3};"
        : "+f"(c[0]), "+f"(c[1]), "+f"(c[2]), "+f"(c[3])
        : "r"(a0), "r"(a1), "r"(a2), "r"(a3), "r"(b0), "r"(b1));
}

// ---------------------------------------------------------------------------
// Prepass: round float array to tf32
// ---------------------------------------------------------------------------
__global__ __launch_bounds__(256) void round_tf32_kernel(
    const float* __restrict__ src, float* __restrict__ dst, int n4)
{
    int i = blockIdx.x * blockDim.x + threadIdx.x;
    if (i < n4) {
        float4 v = ((const float4*)src)[i];
        v.x = roundtf(v.x); v.y = roundtf(v.y);
        v.z = roundtf(v.z); v.w = roundtf(v.w);
        ((float4*)dst)[i] = v;
    }
}

// ---------------------------------------------------------------------------
// tf32 mma.sync GEMM, ldmatrix fragments, 2 CTAs/SM.
// Block 128x128, BK=32, 256 threads (8 warps, warp tile 64x32).
// 3-stage cp.async pipeline, wait_group<=1, ONE barrier per stage.
// smem 110.6KB, <=128 regs -> occupancy 2.
// ---------------------------------------------------------------------------
#define RS    36
#define BUFE  (128*RS)
#define GEMM_SMEM (6*BUFE*4)           // 110592 bytes

__global__ __launch_bounds__(256, 2) void gemm_mma(
    const float* __restrict__ A, const float* __restrict__ Bw,
    const float* __restrict__ bias, int M, int N, int K, int mode,
    float* __restrict__ Cout)
{
    extern __shared__ float sm[];

    const int tid = threadIdx.x, lane = tid & 31, wid = tid >> 5;
    const int bm = blockIdx.y * 128, bn = blockIdx.x * 128;
    const int wm = (wid & 1) * 64, wn = (wid >> 1) * 32;
    const int gr = lane >> 2, lc = lane & 3;

    uint32_t sA[3], sB[3];
#pragma unroll
    for (int i = 0; i < 3; i++) {
        sA[i] = smem_u32(sm + i * BUFE);
        sB[i] = smem_u32(sm + (3 + i) * BUFE);
    }

    float c[4][4][4];
#pragma unroll
    for (int i = 0; i < 4; i++)
#pragma unroll
        for (int j = 0; j < 4; j++)
#pragma unroll
            for (int r = 0; r < 4; r++) c[i][j][r] = 0.f;

    const int row_l = tid >> 3;          // 0..31
    const int c4 = tid & 7;

    int gA[4], gB[4];
#pragma unroll
    for (int it = 0; it < 4; it++) {
        int row = row_l + it * 32;
        int ga = bm + row; if (ga > M - 1) ga = M - 1;
        int gb = bn + row; if (gb > N - 1) gb = N - 1;
        gA[it] = ga; gB[it] = gb;
    }
    const uint32_t soff = (uint32_t)(row_l * RS + c4 * 4) * 4;
    const uint32_t sstep = (uint32_t)(32 * RS) * 4;

    // ldmatrix coords (word units)
    const int lmA_row = wm + (lane & 15);            // + mt*16
    const int lmA_col = (lane >> 4) << 2;
    const int lmB_row = wn + (lane & 7) + ((lane >> 4) & 1) * 8;  // + pr*16
    const int lmB_col = ((lane >> 3) & 1) * 4;

    const int S = K / 32;

#pragma unroll
    for (int ps = 0; ps < 2; ps++) {
        const int k0 = ps * 32;
#pragma unroll
        for (int it = 0; it < 4; it++) {
            cp16(sA[ps] + soff + it * sstep, A  + (size_t)gA[it] * K + k0 + c4 * 4);
            cp16(sB[ps] + soff + it * sstep, Bw + (size_t)gB[it] * K + k0 + c4 * 4);
        }
        cp_commit();
    }

    int cb = 0, lb = 2;
    for (int s = 0; s < S; s++) {
        cp_wait1();
        __syncthreads();

        const int ls = s + 2;
        if (ls < S) {
            const int k0 = ls * 32;
#pragma unroll
            for (int it = 0; it < 4; it++) {
                cp16(sA[lb] + soff + it * sstep, A  + (size_t)gA[it] * K + k0 + c4 * 4);
                cp16(sB[lb] + soff + it * sstep, Bw + (size_t)gB[it] * K + k0 + c4 * 4);
            }
        }
        cp_commit();

        const uint32_t Abase = sA[cb];
        const uint32_t Bbase = sB[cb];
#pragma unroll
        for (int kk = 0; kk < 4; kk++) {
            const int kbase = kk * 8;
            uint32_t af[4][4];
#pragma unroll
            for (int mt = 0; mt < 4; mt++)
                ldsm4(af[mt][0], af[mt][1], af[mt][2], af[mt][3],
                      Abase + (uint32_t)((lmA_row + mt * 16) * RS + kbase + lmA_col) * 4);
            uint32_t bf[4][2];
#pragma unroll
            for (int pr = 0; pr < 2; pr++)
                ldsm4(bf[2*pr][0], bf[2*pr][1], bf[2*pr+1][0], bf[2*pr+1][1],
                      Bbase + (uint32_t)((lmB_row + pr * 16) * RS + kbase + lmB_col) * 4);
#pragma unroll
            for (int mt = 0; mt < 4; mt++)
#pragma unroll
                for (int nt = 0; nt < 4; nt++)
                    mma_tf32(c[mt][nt], af[mt][0], af[mt][1], af[mt][2], af[mt][3],
                             bf[nt][0], bf[nt][1]);
        }
        cb = (cb + 1) % 3;
        lb = (lb + 1) % 3;
    }

#pragma unroll
    for (int mt = 0; mt < 4; mt++) {
        const int r0 = bm + wm + mt * 16 + gr;
        const int r1 = r0 + 8;
#pragma unroll
        for (int nt = 0; nt < 4; nt++) {
            const int nc = bn + wn + nt * 8 + lc * 2;
            float2 bv = *(const float2*)(bias + nc);
            float2 o0 = { c[mt][nt][0] + bv.x, c[mt][nt][1] + bv.y };
            float2 o1 = { c[mt][nt][2] + bv.x, c[mt][nt][3] + bv.y };
            if (mode == 0) {
                const int which = nc / CT;
                const int rem = nc % CT;
                const int h = rem / DT, d0 = rem % DT;
                const int wi = d0 >> 1;
#pragma unroll
                for (int rr = 0; rr < 2; rr++) {
                    const int m = rr ? r1 : r0;
                    if (m >= M) continue;
                    float2 o = rr ? o1 : o0;
                    const int b_ = m / NT, tok = m % NT;
                    const size_t base = ((size_t)(b_ * HT + h)) * NT + tok;
                    if (which == 0) {
                        uint32_t hi, lo;
                        bf16split(o.x * 0.125f, o.y * 0.125f, hi, lo);
                        g_qh[base * 32 + wi] = hi;
                        g_ql[base * 32 + wi] = lo;
                    } else if (which == 1) {
                        uint32_t hi, lo;
                        bf16split(o.x, o.y, hi, lo);
                        g_kh[base * 32 + wi] = hi;
                        g_kl[base * 32 + wi] = lo;
                    } else {
                        *(float2*)(g_v + base * DT + d0) =
                            make_float2(roundtf(o.x), roundtf(o.y));
                    }
                }
            } else {
                if (r0 < M) *(float2*)(Cout + (size_t)r0 * N + nc) = o0;
                if (r1 < M) *(float2*)(Cout + (size_t)r1 * N + nc) = o1;
            }
        }
    }
}

// ---------------------------------------------------------------------------
// Fused attention (R12 proven: bf16-split QK via ldsm + tf32 PV scalar-frag)
// ---------------------------------------------------------------------------
#define RSQW 36
#define SVR  72
#define SSP  228
#define OFF_QH 0
#define OFF_QL (64*RSQW)
#define OFF_KH (2*64*RSQW)
#define OFF_KL (2*64*RSQW + 224*RSQW)
#define OFF_VS (2*64*RSQW + 2*224*RSQW)
#define OFF_SS OFF_KH
#define ATT_FLOATS (OFF_VS + 200*SVR)
#define ATT_SMEM (ATT_FLOATS*4)

__global__ __launch_bounds__(512) void attn_mma()
{
    extern __shared__ float smf[];
    const uint32_t sb = smem_u32(smf);

    const int tid = threadIdx.x, lane = tid & 31, wid = tid >> 5;
    const int gr = lane >> 2, lc = lane & 3;
    const int blk = blockIdx.x;
    const int bh = blk >> 2, qt = blk & 3;
    const int qbase = qt * 64;
    const int b = bh / HT, h = bh % HT;
    const int rows_valid = (NT - qbase < 64) ? (NT - qbase) : 64;

    const uint32_t* Gqh = g_qh + (size_t)bh * NT * 32;
    const uint32_t* Gql = g_ql + (size_t)bh * NT * 32;
    const uint32_t* Gkh = g_kh + (size_t)bh * NT * 32;
    const uint32_t* Gkl = g_kl + (size_t)bh * NT * 32;
    const float*    Gv  = g_v  + (size_t)bh * NT * DT;

    {
        int r = tid >> 3, w4 = (tid & 7) * 4;
        int src = qbase + r; if (src > NT - 1) src = NT - 1;
        cp16(sb + (OFF_QH + r * RSQW + w4) * 4, Gqh + (size_t)src * 32 + w4);
        cp16(sb + (OFF_QL + r * RSQW + w4) * 4, Gql + (size_t)src * 32 + w4);
    }
    for (int i = tid; i < 224 * 8; i += 512) {
        int r = i >> 3, w4 = (i & 7) * 4;
        if (r < NT) {
            cp16(sb + (OFF_KH + r * RSQW + w4) * 4, Gkh + (size_t)r * 32 + w4);
            cp16(sb + (OFF_KL + r * RSQW + w4) * 4, Gkl + (size_t)r * 32 + w4);
        } else {
            *(float4*)(smf + OFF_KH + r * RSQW + w4) = make_float4(0.f,0.f,0.f,0.f);
            *(float4*)(smf + OFF_KL + r * RSQW + w4) = make_float4(0.f,0.f,0.f,0.f);
        }
    }
    for (int i = tid; i < 200 * 16; i += 512) {
        int r = i >> 4, c4 = (i & 15) * 4;
        if (r < NT) cp16(sb + (OFF_VS + r * SVR + c4) * 4, Gv + (size_t)r * DT + c4);
        else *(float4*)(smf + OFF_VS + r * SVR + c4) = make_float4(0.f,0.f,0.f,0.f);
    }
    cp_commit();
    cp_wait0();
    __syncthreads();

    const int wm = (wid & 3) * 16;
    const int wn = (wid >> 2) * 56;

    const int lmA_row = wm + (lane & 15);
    const int lmA_col = (lane >> 4) << 2;
    const int lmB_row = wn + (lane & 7) + ((lane >> 4) & 1) * 8;
    const int lmB_col = ((lane >> 3) & 1) * 4;
    const int lmB2_row = wn + 48 + (lane & 7);
    const int lmB2_col = ((lane >> 3) & 1) * 4;

    const uint32_t sQH = sb + OFF_QH * 4;
    const uint32_t sQL = sb + OFF_QL * 4;
    const uint32_t sKH = sb + OFF_KH * 4;
    const uint32_t sKL = sb + OFF_KL * 4;

    float cS[7][4];
#pragma unroll
    for (int nt = 0; nt < 7; nt++)
#pragma unroll
        for (int r = 0; r < 4; r++) cS[nt][r] = 0.f;

#pragma unroll
    for (int kk = 0; kk < 4; kk++) {
        const int kbw = kk * 8;
        uint32_t ah[4], al[4];
        ldsm4(ah[0], ah[1], ah[2], ah[3],
              sQH + (uint32_t)(lmA_row * RSQW + kbw + lmA_col) * 4);
        ldsm4(al[0], al[1], al[2], al[3],
              sQL + (uint32_t)(lmA_row * RSQW + kbw + lmA_col) * 4);

        uint32_t bhv[7][2], blv[7][2];
#pragma unroll
        for (int pr = 0; pr < 3; pr++) {
            ldsm4(bhv[2*pr][0], bhv[2*pr][1], bhv[2*pr+1][0], bhv[2*pr+1][1],
                  sKH + (uint32_t)((lmB_row + pr * 16) * RSQW + kbw + lmB_col) * 4);
            ldsm4(blv[2*pr][0], blv[2*pr][1], blv[2*pr+1][0], blv[2*pr+1][1],
                  sKL + (uint32_t)((lmB_row + pr * 16) * RSQW + kbw + lmB_col) * 4);
        }
        ldsm2(bhv[6][0], bhv[6][1],
              sKH + (uint32_t)(lmB2_row * RSQW + kbw + lmB2_col) * 4);
        ldsm2(blv[6][0], blv[6][1],
              sKL + (uint32_t)(lmB2_row * RSQW + kbw + lmB2_col) * 4);

#pragma unroll
        for (int nt = 0; nt < 7; nt++) {
            mma_bf16(cS[nt], ah[0], ah[1], ah[2], ah[3], bhv[nt][0], bhv[nt][1]);
            mma_bf16(cS[nt], ah[0], ah[1], ah[2], ah[3], blv[nt][0], blv[nt][1]);
            mma_bf16(cS[nt], al[0], al[1], al[2], al[3], bhv[nt][0], bhv[nt][1]);
        }
    }
    __syncthreads();

    float* Ss = smf + OFF_SS;
    {
        const int row = wm + gr;
#pragma unroll
        for (int nt = 0; nt < 7; nt++) {
            const int col = wn + nt * 8 + 2 * lc;
            *(float2*)(Ss + row * SSP + col)       = make_float2(cS[nt][0], cS[nt][1]);
            *(float2*)(Ss + (row + 8) * SSP + col) = make_float2(cS[nt][2], cS[nt][3]);
        }
    }
    __syncthreads();

    for (int r4 = 0; r4 < 4; r4++) {
        const int r = wid * 4 + r4;
        float vx[7];
        float mx = -FLT_MAX;
#pragma unroll
        for (int t = 0; t < 7; t++) {
            int j = lane + 32 * t;
            vx[t] = (j < NT) ? Ss[r * SSP + j] : -FLT_MAX;
            mx = fmaxf(mx, vx[t]);
        }
#pragma unroll
        for (int o = 16; o; o >>= 1) mx = fmaxf(mx, __shfl_xor_sync(~0u, mx, o));
        float sum = 0.f;
#pragma unroll
        for (int t = 0; t < 7; t++) {
            int j = lane + 32 * t;
            float e = (j < NT) ? __expf(vx[t] - mx) : 0.f;
            vx[t] = e;
            sum += e;
        }
#pragma unroll
        for (int o = 16; o; o >>= 1) sum += __shfl_xor_sync(~0u, sum, o);
        float inv = 1.f / sum;
#pragma unroll
        for (int t = 0; t < 7; t++) {
            int j = lane + 32 * t;
            if (j < NT)        Ss[r * SSP + j] = roundtf(vx[t] * inv);
            else if (j < 200)  Ss[r * SSP + j] = 0.f;
        }
    }
    __syncthreads();

    const float* Vs = smf + OFF_VS;
    const int wn2 = (wid >> 2) * 16;
    float cO[2][4];
#pragma unroll
    for (int nt = 0; nt < 2; nt++)
#pragma unroll
        for (int r = 0; r < 4; r++) cO[nt][r] = 0.f;

#pragma unroll
    for (int kk = 0; kk < 25; kk++) {
        const int kb = kk * 8;
        uint32_t af[4];
        {
            const uint32_t* p0 = (const uint32_t*)(Ss + (wm + gr) * SSP + kb + lc);
            af[0] = p0[0]; af[1] = p0[8 * SSP]; af[2] = p0[4]; af[3] = p0[8 * SSP + 4];
        }
        uint32_t bf[2][2];
#pragma unroll
        for (int nt = 0; nt < 2; nt++) {
            const uint32_t* p = (const uint32_t*)(Vs + (size_t)(kb + lc) * SVR + wn2 + nt * 8 + gr);
            bf[nt][0] = p[0];
            bf[nt][1] = p[4 * SVR];
        }
#pragma unroll
        for (int nt = 0; nt < 2; nt++)
            mma_tf32(cO[nt], af[0], af[1], af[2], af[3], bf[nt][0], bf[nt][1]);
    }
    {
        const int lr0 = wm + gr;
        const int lr1 = lr0 + 8;
#pragma unroll
        for (int nt = 0; nt < 2; nt++) {
            const int d = wn2 + nt * 8 + 2 * lc;
            if (lr0 < rows_valid)
                *(float2*)(g_ao + ((size_t)(b * NT + qbase + lr0)) * CT + h * DT + d)
                    = make_float2(roundtf(cO[nt][0]), roundtf(cO[nt][1]));
            if (lr1 < rows_valid)
                *(float2*)(g_ao + ((size_t)(b * NT + qbase + lr1)) * CT + h * DT + d)
                    = make_float2(roundtf(cO[nt][2]), roundtf(cO[nt][3]));
        }
    }
}

// ---------------------------------------------------------------------------
// Exact fp32 cls path — dense kernels (R11/R12 proven)
// ---------------------------------------------------------------------------
__global__ __launch_bounds__(256) void cls_qcls(
    const float* __restrict__ x, const float* __restrict__ qkv_w,
    const float* __restrict__ qkv_b)
{
    __shared__ float xs[64 * 132];
    __shared__ float ws[16 * 132];
    const int tid = threadIdx.x;
    const int n0 = blockIdx.x * 16;
    const int tx = tid & 15;
    const int ty = tid >> 4;

    float acc[4] = {0.f, 0.f, 0.f, 0.f};

    for (int c0 = 0; c0 < CT; c0 += 128) {
#pragma unroll
        for (int it = 0; it < 8; it++) {
            int g = tid + it * 256;
            int row = g >> 5, c4 = (g & 31) * 4;
            *(float4*)(xs + row * 132 + c4) =
                *(const float4*)(x + (size_t)row * NT * CT + c0 + c4);
        }
#pragma unroll
        for (int it = 0; it < 2; it++) {
            int g = tid + it * 256;
            if (g < 512) {
                int row = g >> 5, c4 = (g & 31) * 4;
                *(float4*)(ws + row * 132 + c4) =
                    *(const float4*)(qkv_w + (size_t)(n0 + row) * CT + c0 + c4);
            }
        }
        __syncthreads();
        for (int c = 0; c < 128; c++) {
            float wv = ws[tx * 132 + c];
#pragma unroll
            for (int i = 0; i < 4; i++)
                acc[i] += xs[(ty * 4 + i) * 132 + c] * wv;
        }
        __syncthreads();
    }
    float bq = qkv_b[n0 + tx];
#pragma unroll
    for (int i = 0; i < 4; i++)
        g_qc[(size_t)(ty * 4 + i) * CT + n0 + tx] = acc[i] + bq;
}

__global__ __launch_bounds__(256) void cls_wt(
    const float* __restrict__ qkv_w, const float* __restrict__ qkv_b)
{
    __shared__ float qs[64 * 68];
    __shared__ float wks[64 * 68];
    const int tid = threadIdx.x;
    const int c0 = blockIdx.x * 64;
    const int h = blockIdx.y;
    const int tx = tid & 31;
    const int ty = tid >> 5;

#pragma unroll
    for (int it = 0; it < 4; it++) {
        int g = tid + it * 256;
        int row = g >> 4, d4 = (g & 15) * 4;
        *(float4*)(qs + row * 68 + d4) =
            *(const float4*)(g_qc + (size_t)row * CT + h * 64 + d4);
    }
#pragma unroll
    for (int it = 0; it < 4; it++) {
        int g = tid + it * 256;
        int d = g >> 4, c4 = (g & 15) * 4;
        *(float4*)(wks + d * 68 + c4) =
            *(const float4*)(qkv_w + (size_t)(CT + h * 64 + d) * CT + c0 + c4);
    }
    __syncthreads();

    float acc[8][2];
#pragma unroll
    for (int i = 0; i < 8; i++) { acc[i][0] = 0.f; acc[i][1] = 0.f; }
    for (int d = 0; d < 64; d++) {
        float w0 = wks[d * 68 + tx * 2];
        float w1 = wks[d * 68 + tx * 2 + 1];
#pragma unroll
        for (int i = 0; i < 8; i++) {
            float qv = qs[(ty * 8 + i) * 68 + d];
            acc[i][0] += qv * w0;
            acc[i][1] += qv * w1;
        }
    }
#pragma unroll
    for (int i = 0; i < 8; i++) {
        int b = ty * 8 + i;
        g_wt[(size_t)(b * HT + h) * CT + c0 + tx * 2]     = acc[i][0];
        g_wt[(size_t)(b * HT + h) * CT + c0 + tx * 2 + 1] = acc[i][1];
    }

    if (blockIdx.x == 0 && tid < 64) {
        float s = 0.f;
        for (int d = 0; d < 64; d++)
            s += qs[tid * 68 + d] * qkv_b[CT + h * 64 + d];
        g_beta[tid * HT + h] = s;
    }
}

__global__ __launch_bounds__(256) void cls_fused(
    const float* __restrict__ x, float* __restrict__ out_cls)
{
    __shared__ float wts[HT * CT];
    __shared__ float S[HT * 200];
    __shared__ float betas[HT];
    const int b = blockIdx.x;
    const int tid = threadIdx.x, lane = tid & 31, w = tid >> 5;

    for (int i = tid; i < HT * CT / 4; i += 256)
        ((float4*)wts)[i] = ((const float4*)(g_wt + (size_t)b * HT * CT))[i];
    if (tid < HT) betas[tid] = g_beta[b * HT + tid];
    __syncthreads();

    const int jstart = w * 25;
    const int jend = (jstart + 25 < NT) ? jstart + 25 : NT;
    const float* xb = x + (size_t)b * NT * CT;

    for (int jb = jstart; jb < jend; jb += 4) {
        const int nj = (jend - jb < 4) ? (jend - jb) : 4;
        float acc[HT][4];
#pragma unroll
        for (int h = 0; h < HT; h++)
#pragma unroll
            for (int jj = 0; jj < 4; jj++) acc[h][jj] = 0.f;

        int jr[4];
#pragma unroll
        for (int jj = 0; jj < 4; jj++) {
            int j = jb + jj; if (j > NT - 1) j = NT - 1;
            jr[jj] = j;
        }
#pragma unroll 4
        for (int t = 0; t < 24; t++) {
            const int c = lane + 32 * t;
            float xv[4];
#pragma unroll
            for (int jj = 0; jj < 4; jj++) xv[jj] = xb[(size_t)jr[jj] * CT + c];
#pragma unroll
            for (int h = 0; h < HT; h++) {
                float wv = wts[h * CT + c];
#pragma unroll
                for (int jj = 0; jj < 4; jj++) acc[h][jj] += wv * xv[jj];
            }
        }
#pragma unroll
        for (int h = 0; h < HT; h++)
#pragma unroll
            for (int jj = 0; jj < 4; jj++) {
                float s = acc[h][jj];
#pragma unroll
                for (int o = 16; o; o >>= 1) s += __shfl_xor_sync(~0u, s, o);
                if (lane == 0 && jj < nj)
                    S[h * 200 + jb + jj] = (s + betas[h]) * 0.125f;
            }
    }
    __syncthreads();

    for (int hh = w; hh < HT; hh += 8) {
        float vx[7];
        float mx = -FLT_MAX;
#pragma unroll
        for (int t = 0; t < 7; t++) {
            int j = lane + 32 * t;
            vx[t] = (j < NT) ? S[hh * 200 + j] : -FLT_MAX;
            mx = fmaxf(mx, vx[t]);
        }
#pragma unroll
        for (int o = 16; o; o >>= 1) mx = fmaxf(mx, __shfl_xor_sync(~0u, mx, o));
        float sum = 0.f;
#pragma unroll
        for (int t = 0; t < 7; t++) {
            int j = lane + 32 * t;
            float e = (j < NT) ? __expf(vx[t] - mx) : 0.f;
            vx[t] = e;
            sum += e;
        }
#pragma unroll
        for (int o = 16; o; o >>= 1) sum += __shfl_xor_sync(~0u, sum, o);
        float inv = 1.f / sum;
#pragma unroll
        for (int t = 0; t < 7; t++) {
            int j = lane + 32 * t;
            if (j < NT) S[hh * 200 + j] = vx[t] * inv;
        }
    }
    __syncthreads();

    for (int j = 1 + tid; j < NT; j += 256) {
        float s = 0.f;
#pragma unroll
        for (int h = 0; h < HT; h++) s += S[h * 200 + j];
        out_cls[b * (NT - 1) + (j - 1)] = s * (1.f / 12.f);
    }
}

// ---------------------------------------------------------------------------
// Top-k per batch + index broadcast
// ---------------------------------------------------------------------------
__global__ __launch_bounds__(256) void topk_kernel(
    const float* __restrict__ cls, float* __restrict__ out_idx,
    float* __restrict__ out_index)
{
    __shared__ float v[256];
    __shared__ int   id[256];
    const int bb = blockIdx.x;
    const int t = threadIdx.x;

    v[t]  = (t < NT - 1) ? cls[bb * (NT - 1) + t] : -FLT_MAX;
    id[t] = t;
    __syncthreads();

    for (int ksz = 2; ksz <= 256; ksz <<= 1) {
        for (int j = ksz >> 1; j > 0; j >>= 1) {
            int ixj = t ^ j;
            if (ixj > t) {
                float v1 = v[t], v2 = v[ixj];
                int i1 = id[t], i2 = id[ixj];
                bool before = (v1 > v2) || (v1 == v2 && i1 < i2);
                bool desc = ((t & ksz) == 0);
                if (desc ? !before : before) {
                    v[t] = v2; v[ixj] = v1;
                    id[t] = i2; id[ixj] = i1;
                }
            }
            __syncthreads();
        }
    }

    if (t < LEFT) out_idx[bb * LEFT + t] = (float)id[t];
    float* dst = out_index + (size_t)bb * LEFT * CT;
    for (int e = t; e < LEFT * CT; e += 256) dst[e] = (float)id[e / CT];
}

// ---------------------------------------------------------------------------
extern "C" void kernel_launch(void* const* d_in, const int* in_sizes, int n_in,
                              void* d_out, int out_size)
{
    const float* x      = (const float*)d_in[0];
    const float* qkv_w  = (const float*)d_in[1];
    const float* qkv_b  = (const float*)d_in[2];
    const float* proj_w = (const float*)d_in[3];
    const float* proj_b = (const float*)d_in[4];

    float* out_o     = (float*)d_out;
    float* out_index = out_o     + (size_t)BB * NT * CT;
    float* out_idx   = out_index + (size_t)BB * LEFT * CT;
    float* out_cls   = out_idx   + (size_t)BB * LEFT;

    float *ao_ptr, *xr_ptr, *wqr_ptr, *wpr_ptr;
    cudaGetSymbolAddress((void**)&ao_ptr,  g_ao);
    cudaGetSymbolAddress((void**)&xr_ptr,  g_xr);
    cudaGetSymbolAddress((void**)&wqr_ptr, g_wqr);
    cudaGetSymbolAddress((void**)&wpr_ptr, g_wpr);

    cudaFuncSetAttribute(gemm_mma, cudaFuncAttributeMaxDynamicSharedMemorySize, GEMM_SMEM);
    cudaFuncSetAttribute(attn_mma, cudaFuncAttributeMaxDynamicSharedMemorySize, ATT_SMEM);

    const int mby = (MROWS + 127) / 128;   // 99

    // 1-3) prepass rounds
    {
        int n4 = MROWS * CT / 4;
        round_tf32_kernel<<<(n4 + 255) / 256, 256>>>(x, xr_ptr, n4);
        n4 = 3 * CT * CT / 4;
        round_tf32_kernel<<<(n4 + 255) / 256, 256>>>(qkv_w, wqr_ptr, n4);
        n4 = CT * CT / 4;
        round_tf32_kernel<<<(n4 + 255) / 256, 256>>>(proj_w, wpr_ptr, n4);
    }

    // 4) qkv projection (profiled slot; 128x128 tile, 2 CTAs/SM)
    gemm_mma<<<dim3(3 * CT / 128, mby), 256, GEMM_SMEM>>>(
        xr_ptr, wqr_ptr, qkv_b, MROWS, 3 * CT, CT, 0, nullptr);

    // 5) fused attention
    attn_mma<<<BB * HT * 4, 512, ATT_SMEM>>>();

    // 6-8) exact cls path (dense)
    cls_qcls<<<CT / 16, 256>>>(x, qkv_w, qkv_b);
    cls_wt<<<dim3(12, HT), 256>>>(qkv_w, qkv_b);
    cls_fused<<<BB, 256>>>(x, out_cls);

    // 9) output projection
    gemm_mma<<<dim3(CT / 128, mby), 256, GEMM_SMEM>>>(
        ao_ptr, wpr_ptr, proj_b, MROWS, CT, CT, 1, out_o);

    // 10) top-k + index broadcast
    topk_kernel<<<BB, 256>>>(out_cls, out_idx, out_index);
}

// round 15
// speedup vs baseline: 1.0673x; 1.0673x over previous
#include <cuda_runtime.h>
#include <cuda_bf16.h>
#include <cstdint>
#include <float.h>
#include <math.h>

#define BB   64
#define NT   197
#define CT   768
#define HT   12
#define DT   64
#define LEFT 137
#define MROWS (BB*NT)     // 12608

// device scratch
__device__ uint32_t g_qh[BB*HT*NT*32];
__device__ uint32_t g_ql[BB*HT*NT*32];
__device__ uint32_t g_kh[BB*HT*NT*32];
__device__ uint32_t g_kl[BB*HT*NT*32];
__device__ float    g_v [BB*HT*NT*DT];
__device__ float    g_ao[BB*NT*CT];
__device__ float    g_wt[BB*HT*CT];
__device__ float    g_beta[BB*HT];
__device__ float    g_qc[BB*CT];
__device__ float    g_xr[MROWS*CT];
__device__ float    g_wqr[3*CT*CT];
__device__ float    g_wpr[CT*CT];

// ---------------------------------------------------------------------------
// helpers
// ---------------------------------------------------------------------------
__device__ __forceinline__ uint32_t smem_u32(const void* p) {
    uint32_t a;
    asm("{ .reg .u64 t; cvta.to.shared.u64 t, %1; cvt.u32.u64 %0, t; }" : "=r"(a) : "l"(p));
    return a;
}
__device__ __forceinline__ void cp16(uint32_t saddr, const void* g) {
    asm volatile("cp.async.ca.shared.global [%0], [%1], 16;" :: "r"(saddr), "l"(g));
}
__device__ __forceinline__ void cp_commit() {
    asm volatile("cp.async.commit_group;" ::: "memory");
}
__device__ __forceinline__ void cp_wait1() {
    asm volatile("cp.async.wait_group 1;" ::: "memory");
}
__device__ __forceinline__ void cp_wait0() {
    asm volatile("cp.async.wait_group 0;" ::: "memory");
}
__device__ __forceinline__ uint32_t f2tf32(float v) {
    uint32_t r;
    asm("cvt.rna.tf32.f32 %0, %1;" : "=r"(r) : "f"(v));
    return r;
}
__device__ __forceinline__ float roundtf(float v) {
    return __uint_as_float(f2tf32(v));
}
__device__ __forceinline__ uint32_t packbf(float x, float y) {
    __nv_bfloat162 t = __floats2bfloat162_rn(x, y);
    return *reinterpret_cast<uint32_t*>(&t);
}
__device__ __forceinline__ void bf16split(float x, float y, uint32_t& hi, uint32_t& lo) {
    float xh = __bfloat162float(__float2bfloat16_rn(x));
    float yh = __bfloat162float(__float2bfloat16_rn(y));
    hi = packbf(xh, yh);
    lo = packbf(x - xh, y - yh);
}
__device__ __forceinline__ void ldsm4(uint32_t& r0, uint32_t& r1, uint32_t& r2,
                                      uint32_t& r3, uint32_t sa) {
    asm volatile("ldmatrix.sync.aligned.m8n8.x4.shared.b16 {%0,%1,%2,%3}, [%4];"
                 : "=r"(r0), "=r"(r1), "=r"(r2), "=r"(r3) : "r"(sa));
}
__device__ __forceinline__ void mma_tf32(float c[4], uint32_t a0, uint32_t a1,
                                         uint32_t a2, uint32_t a3,
                                         uint32_t b0, uint32_t b1) {
    asm volatile(
        "mma.sync.aligned.m16n8k8.row.col.f32.tf32.tf32.f32 "
        "{%0,%1,%2,%3}, {%4,%5,%6,%7}, {%8,%9}, {%0,%1,%2,%3};"
        : "+f"(c[0]), "+f"(c[1]), "+f"(c[2]), "+f"(c[3])
        : "r"(a0), "r"(a1), "r"(a2), "r"(a3), "r"(b0), "r"(b1));
}
__device__ __forceinline__ void mma_bf16(float c[4], uint32_t a0, uint32_t a1,
                                         uint32_t a2, uint32_t a3,
                                         uint32_t b0, uint32_t b1) {
    asm volatile(
        "mma.sync.aligned.m16n8k16.row.col.f32.bf16.bf16.f32 "
        "{%0,%1,%2,%3}, {%4,%5,%6,%7}, {%8,%9}, {%0,%1,%2,%3};"
        : "+f"(c[0]), "+f"(c[1]), "+f"(c[2]), "+f"(c[3])
        : "r"(a0), "r"(a1), "r"(a2), "r"(a3), "r"(b0), "r"(b1));
}

// ---------------------------------------------------------------------------
// Prepass: round float array to tf32
// ---------------------------------------------------------------------------
__global__ __launch_bounds__(256) void round_tf32_kernel(
    const float* __restrict__ src, float* __restrict__ dst, int n4)
{
    int i = blockIdx.x * blockDim.x + threadIdx.x;
    if (i < n4) {
        float4 v = ((const float4*)src)[i];
        v.x = roundtf(v.x); v.y = roundtf(v.y);
        v.z = roundtf(v.z); v.w = roundtf(v.w);
        ((float4*)dst)[i] = v;
    }
}

// ---------------------------------------------------------------------------
// tf32 mma.sync GEMM with ldmatrix fragments. (R12 proven — DO NOT TOUCH)
// Block 128x256, BK=32, 512 threads. 3-stage cp.async, wait<=1, one barrier.
// ---------------------------------------------------------------------------
#define RS    36
#define BUFA  (128*RS)
#define BUFB  (256*RS)
#define GEMM_SMEM ((3*BUFA + 3*BUFB)*4)

__global__ __launch_bounds__(512) void gemm_mma(
    const float* __restrict__ A, const float* __restrict__ Bw,
    const float* __restrict__ bias, int M, int N, int K, int mode,
    float* __restrict__ Cout)
{
    extern __shared__ float sm[];

    const int tid = threadIdx.x, lane = tid & 31, wid = tid >> 5;
    const int bm = blockIdx.y * 128, bn = blockIdx.x * 256;
    const int wm = (wid & 3) * 32, wn = (wid >> 2) * 64;
    const int gr = lane >> 2, lc = lane & 3;

    uint32_t sA[3], sB[3];
#pragma unroll
    for (int i = 0; i < 3; i++) {
        sA[i] = smem_u32(sm + i * BUFA);
        sB[i] = smem_u32(sm + 3 * BUFA + i * BUFB);
    }

    float c[2][8][4];
#pragma unroll
    for (int i = 0; i < 2; i++)
#pragma unroll
        for (int j = 0; j < 8; j++)
#pragma unroll
            for (int r = 0; r < 4; r++) c[i][j][r] = 0.f;

    const int row_l = tid >> 3;
    const int c4 = tid & 7;

    int gA[2], gB[4];
#pragma unroll
    for (int it = 0; it < 2; it++) {
        int ga = bm + row_l + it * 64; if (ga > M - 1) ga = M - 1;
        gA[it] = ga;
    }
#pragma unroll
    for (int it = 0; it < 4; it++) {
        int gb = bn + row_l + it * 64; if (gb > N - 1) gb = N - 1;
        gB[it] = gb;
    }
    const uint32_t soff = (uint32_t)(row_l * RS + c4 * 4) * 4;
    const uint32_t sstep = (uint32_t)(64 * RS) * 4;

    const int lmA_row = wm + (lane & 15);
    const int lmA_col = (lane >> 4) << 2;
    const int lmB_row = wn + (lane & 7) + ((lane >> 4) & 1) * 8;
    const int lmB_col = ((lane >> 3) & 1) * 4;

    const int S = K / 32;

#pragma unroll
    for (int ps = 0; ps < 2; ps++) {
        const int k0 = ps * 32;
#pragma unroll
        for (int it = 0; it < 2; it++)
            cp16(sA[ps] + soff + it * sstep, A  + (size_t)gA[it] * K + k0 + c4 * 4);
#pragma unroll
        for (int it = 0; it < 4; it++)
            cp16(sB[ps] + soff + it * sstep, Bw + (size_t)gB[it] * K + k0 + c4 * 4);
        cp_commit();
    }

    int cb = 0, lb = 2;
    for (int s = 0; s < S; s++) {
        cp_wait1();
        __syncthreads();

        const int ls = s + 2;
        if (ls < S) {
            const int k0 = ls * 32;
#pragma unroll
            for (int it = 0; it < 2; it++)
                cp16(sA[lb] + soff + it * sstep, A  + (size_t)gA[it] * K + k0 + c4 * 4);
#pragma unroll
            for (int it = 0; it < 4; it++)
                cp16(sB[lb] + soff + it * sstep, Bw + (size_t)gB[it] * K + k0 + c4 * 4);
        }
        cp_commit();

        const uint32_t Abase = sA[cb];
        const uint32_t Bbase = sB[cb];
#pragma unroll
        for (int kk = 0; kk < 4; kk++) {
            const int kbase = kk * 8;
            uint32_t af[2][4];
#pragma unroll
            for (int mt = 0; mt < 2; mt++)
                ldsm4(af[mt][0], af[mt][1], af[mt][2], af[mt][3],
                      Abase + (uint32_t)((lmA_row + mt * 16) * RS + kbase + lmA_col) * 4);
            uint32_t bf[8][2];
#pragma unroll
            for (int pr = 0; pr < 4; pr++)
                ldsm4(bf[2*pr][0], bf[2*pr][1], bf[2*pr+1][0], bf[2*pr+1][1],
                      Bbase + (uint32_t)((lmB_row + pr * 16) * RS + kbase + lmB_col) * 4);
#pragma unroll
            for (int mt = 0; mt < 2; mt++)
#pragma unroll
                for (int nt = 0; nt < 8; nt++)
                    mma_tf32(c[mt][nt], af[mt][0], af[mt][1], af[mt][2], af[mt][3],
                             bf[nt][0], bf[nt][1]);
        }
        cb = (cb + 1) % 3;
        lb = (lb + 1) % 3;
    }

#pragma unroll
    for (int mt = 0; mt < 2; mt++) {
        const int r0 = bm + wm + mt * 16 + gr;
        const int r1 = r0 + 8;
#pragma unroll
        for (int nt = 0; nt < 8; nt++) {
            const int nc = bn + wn + nt * 8 + lc * 2;
            float2 bv = *(const float2*)(bias + nc);
            float2 o0 = { c[mt][nt][0] + bv.x, c[mt][nt][1] + bv.y };
            float2 o1 = { c[mt][nt][2] + bv.x, c[mt][nt][3] + bv.y };
            if (mode == 0) {
                const int which = nc / CT;
                const int rem = nc % CT;
                const int h = rem / DT, d0 = rem % DT;
                const int wi = d0 >> 1;
#pragma unroll
                for (int rr = 0; rr < 2; rr++) {
                    const int m = rr ? r1 : r0;
                    if (m >= M) continue;
                    float2 o = rr ? o1 : o0;
                    const int b_ = m / NT, tok = m % NT;
                    const size_t base = ((size_t)(b_ * HT + h)) * NT + tok;
                    if (which == 0) {
                        uint32_t hi, lo;
                        bf16split(o.x * 0.125f, o.y * 0.125f, hi, lo);
                        g_qh[base * 32 + wi] = hi;
                        g_ql[base * 32 + wi] = lo;
                    } else if (which == 1) {
                        uint32_t hi, lo;
                        bf16split(o.x, o.y, hi, lo);
                        g_kh[base * 32 + wi] = hi;
                        g_kl[base * 32 + wi] = lo;
                    } else {
                        *(float2*)(g_v + base * DT + d0) =
                            make_float2(roundtf(o.x), roundtf(o.y));
                    }
                }
            } else {
                if (r0 < M) *(float2*)(Cout + (size_t)r0 * N + nc) = o0;
                if (r1 < M) *(float2*)(Cout + (size_t)r1 * N + nc) = o1;
            }
        }
    }
}

// ---------------------------------------------------------------------------
// Fused attention, QTILE=128: one block per (b,h,q-half). grid = BB*HT*2.
// 512 threads. bf16-split QK (ldsm) + tf32 PV (scalar V frags, R12-style).
// SMEM: Qh|Ql (128x36 ea) | SS-region (aliases Kh|Kl 224x36 ea; Ss 128x228)
//       | Vs (200x72).  Total 211200 B.
// ---------------------------------------------------------------------------
#define RSQW 36
#define SVR  72
#define SSP  228
#define QTL  128
#define OFF_QH 0
#define OFF_QL (QTL*RSQW)                      // 4608
#define OFF_KH (2*QTL*RSQW)                    // 9216
#define OFF_KL (2*QTL*RSQW + 224*RSQW)         // 17280
#define OFF_SS OFF_KH
#define OFF_VS (OFF_SS + QTL*SSP)              // 9216+29184 = 38400
#define ATT_FLOATS (OFF_VS + 200*SVR)          // 52800
#define ATT_SMEM (ATT_FLOATS*4)                // 211200 B

__global__ __launch_bounds__(512) void attn_mma()
{
    extern __shared__ float smf[];
    const uint32_t sb = smem_u32(smf);

    const int tid = threadIdx.x, lane = tid & 31, wid = tid >> 5;
    const int gr = lane >> 2, lc = lane & 3;
    const int blk = blockIdx.x;
    const int bh = blk >> 1, qt = blk & 1;
    const int qbase = qt * QTL;
    const int b = bh / HT, h = bh % HT;
    const int rows_valid = (NT - qbase < QTL) ? (NT - qbase) : QTL;

    const uint32_t* Gqh = g_qh + (size_t)bh * NT * 32;
    const uint32_t* Gql = g_ql + (size_t)bh * NT * 32;
    const uint32_t* Gkh = g_kh + (size_t)bh * NT * 32;
    const uint32_t* Gkl = g_kl + (size_t)bh * NT * 32;
    const float*    Gv  = g_v  + (size_t)bh * NT * DT;

    // ---- staging ----
    for (int i = tid; i < QTL * 8; i += 512) {
        int r = i >> 3, w4 = (i & 7) * 4;
        int src = qbase + r; if (src > NT - 1) src = NT - 1;
        cp16(sb + (OFF_QH + r * RSQW + w4) * 4, Gqh + (size_t)src * 32 + w4);
        cp16(sb + (OFF_QL + r * RSQW + w4) * 4, Gql + (size_t)src * 32 + w4);
    }
    for (int i = tid; i < 224 * 8; i += 512) {
        int r = i >> 3, w4 = (i & 7) * 4;
        if (r < NT) {
            cp16(sb + (OFF_KH + r * RSQW + w4) * 4, Gkh + (size_t)r * 32 + w4);
            cp16(sb + (OFF_KL + r * RSQW + w4) * 4, Gkl + (size_t)r * 32 + w4);
        } else {
            *(float4*)(smf + OFF_KH + r * RSQW + w4) = make_float4(0.f,0.f,0.f,0.f);
            *(float4*)(smf + OFF_KL + r * RSQW + w4) = make_float4(0.f,0.f,0.f,0.f);
        }
    }
    for (int i = tid; i < 200 * 16; i += 512) {
        int r = i >> 4, c4 = (i & 15) * 4;
        if (r < NT) cp16(sb + (OFF_VS + r * SVR + c4) * 4, Gv + (size_t)r * DT + c4);
        else *(float4*)(smf + OFF_VS + r * SVR + c4) = make_float4(0.f,0.f,0.f,0.f);
    }
    cp_commit();
    cp_wait0();
    __syncthreads();

    // ---- QK^T: bf16 split, warp = (m-tile of 16) x (112 cols = 14 n8-tiles)
    const int wm = (wid & 7) * 16;
    const int wn = (wid >> 3) * 112;

    const int lmA_row = wm + (lane & 15);
    const int lmA_col = (lane >> 4) << 2;
    const int lmB_row = wn + (lane & 7) + ((lane >> 4) & 1) * 8;   // + pr*16
    const int lmB_col = ((lane >> 3) & 1) * 4;

    const uint32_t sQH = sb + OFF_QH * 4;
    const uint32_t sQL = sb + OFF_QL * 4;
    const uint32_t sKH = sb + OFF_KH * 4;
    const uint32_t sKL = sb + OFF_KL * 4;

    float cS[14][4];
#pragma unroll
    for (int nt = 0; nt < 14; nt++)
#pragma unroll
        for (int r = 0; r < 4; r++) cS[nt][r] = 0.f;

#pragma unroll
    for (int kk = 0; kk < 4; kk++) {
        const int kbw = kk * 8;
        uint32_t ah[4], al[4];
        ldsm4(ah[0], ah[1], ah[2], ah[3],
              sQH + (uint32_t)(lmA_row * RSQW + kbw + lmA_col) * 4);
        ldsm4(al[0], al[1], al[2], al[3],
              sQL + (uint32_t)(lmA_row * RSQW + kbw + lmA_col) * 4);

#pragma unroll
        for (int pr = 0; pr < 7; pr++) {
            uint32_t bh0, bh1, bh2, bh3, bl0, bl1, bl2, bl3;
            ldsm4(bh0, bh1, bh2, bh3,
                  sKH + (uint32_t)((lmB_row + pr * 16) * RSQW + kbw + lmB_col) * 4);
            ldsm4(bl0, bl1, bl2, bl3,
                  sKL + (uint32_t)((lmB_row + pr * 16) * RSQW + kbw + lmB_col) * 4);
            mma_bf16(cS[2*pr],   ah[0], ah[1], ah[2], ah[3], bh0, bh1);
            mma_bf16(cS[2*pr],   ah[0], ah[1], ah[2], ah[3], bl0, bl1);
            mma_bf16(cS[2*pr],   al[0], al[1], al[2], al[3], bh0, bh1);
            mma_bf16(cS[2*pr+1], ah[0], ah[1], ah[2], ah[3], bh2, bh3);
            mma_bf16(cS[2*pr+1], ah[0], ah[1], ah[2], ah[3], bl2, bl3);
            mma_bf16(cS[2*pr+1], al[0], al[1], al[2], al[3], bh2, bh3);
        }
    }
    __syncthreads();     // K region dead before Ss overwrites it

    float* Ss = smf + OFF_SS;
    {
        const int row = wm + gr;
#pragma unroll
        for (int nt = 0; nt < 14; nt++) {
            const int col = wn + nt * 8 + 2 * lc;
            *(float2*)(Ss + row * SSP + col)       = make_float2(cS[nt][0], cS[nt][1]);
            *(float2*)(Ss + (row + 8) * SSP + col) = make_float2(cS[nt][2], cS[nt][3]);
        }
    }
    __syncthreads();

    // ---- softmax: warp wid owns rows wid*8 .. wid*8+7 ----
    for (int r8 = 0; r8 < 8; r8++) {
        const int r = wid * 8 + r8;
        float vx[7];
        float mx = -FLT_MAX;
#pragma unroll
        for (int t = 0; t < 7; t++) {
            int j = lane + 32 * t;
            vx[t] = (j < NT) ? Ss[r * SSP + j] : -FLT_MAX;
            mx = fmaxf(mx, vx[t]);
        }
#pragma unroll
        for (int o = 16; o; o >>= 1) mx = fmaxf(mx, __shfl_xor_sync(~0u, mx, o));
        float sum = 0.f;
#pragma unroll
        for (int t = 0; t < 7; t++) {
            int j = lane + 32 * t;
            float e = (j < NT) ? __expf(vx[t] - mx) : 0.f;
            vx[t] = e;
            sum += e;
        }
#pragma unroll
        for (int o = 16; o; o >>= 1) sum += __shfl_xor_sync(~0u, sum, o);
        float inv = 1.f / sum;
#pragma unroll
        for (int t = 0; t < 7; t++) {
            int j = lane + 32 * t;
            if (j < NT)        Ss[r * SSP + j] = roundtf(vx[t] * inv);
            else if (j < 200)  Ss[r * SSP + j] = 0.f;
        }
    }
    __syncthreads();

    // ---- PV: tf32; warp = (m-tile of 16) x (32 cols = 4 n8-tiles) ----
    const float* Vs = smf + OFF_VS;
    const int wn2 = (wid >> 3) * 32;
    float cO[4][4];
#pragma unroll
    for (int nt = 0; nt < 4; nt++)
#pragma unroll
        for (int r = 0; r < 4; r++) cO[nt][r] = 0.f;

#pragma unroll
    for (int kk = 0; kk < 25; kk++) {
        const int kb = kk * 8;
        uint32_t af[4];
        {
            const uint32_t* p0 = (const uint32_t*)(Ss + (wm + gr) * SSP + kb + lc);
            af[0] = p0[0]; af[1] = p0[8 * SSP]; af[2] = p0[4]; af[3] = p0[8 * SSP + 4];
        }
        uint32_t bf[4][2];
#pragma unroll
        for (int nt = 0; nt < 4; nt++) {
            const uint32_t* p = (const uint32_t*)(Vs + (size_t)(kb + lc) * SVR + wn2 + nt * 8 + gr);
            bf[nt][0] = p[0];
            bf[nt][1] = p[4 * SVR];
        }
#pragma unroll
        for (int nt = 0; nt < 4; nt++)
            mma_tf32(cO[nt], af[0], af[1], af[2], af[3], bf[nt][0], bf[nt][1]);
    }
    {
        const int lr0 = wm + gr;
        const int lr1 = lr0 + 8;
#pragma unroll
        for (int nt = 0; nt < 4; nt++) {
            const int d = wn2 + nt * 8 + 2 * lc;
            if (lr0 < rows_valid)
                *(float2*)(g_ao + ((size_t)(b * NT + qbase + lr0)) * CT + h * DT + d)
                    = make_float2(roundtf(cO[nt][0]), roundtf(cO[nt][1]));
            if (lr1 < rows_valid)
                *(float2*)(g_ao + ((size_t)(b * NT + qbase + lr1)) * CT + h * DT + d)
                    = make_float2(roundtf(cO[nt][2]), roundtf(cO[nt][3]));
        }
    }
}

// ---------------------------------------------------------------------------
// Exact fp32 cls path — dense kernels (R11/R12 proven)
// ---------------------------------------------------------------------------
__global__ __launch_bounds__(256) void cls_qcls(
    const float* __restrict__ x, const float* __restrict__ qkv_w,
    const float* __restrict__ qkv_b)
{
    __shared__ float xs[64 * 132];
    __shared__ float ws[16 * 132];
    const int tid = threadIdx.x;
    const int n0 = blockIdx.x * 16;
    const int tx = tid & 15;
    const int ty = tid >> 4;

    float acc[4] = {0.f, 0.f, 0.f, 0.f};

    for (int c0 = 0; c0 < CT; c0 += 128) {
#pragma unroll
        for (int it = 0; it < 8; it++) {
            int g = tid + it * 256;
            int row = g >> 5, c4 = (g & 31) * 4;
            *(float4*)(xs + row * 132 + c4) =
                *(const float4*)(x + (size_t)row * NT * CT + c0 + c4);
        }
#pragma unroll
        for (int it = 0; it < 2; it++) {
            int g = tid + it * 256;
            if (g < 512) {
                int row = g >> 5, c4 = (g & 31) * 4;
                *(float4*)(ws + row * 132 + c4) =
                    *(const float4*)(qkv_w + (size_t)(n0 + row) * CT + c0 + c4);
            }
        }
        __syncthreads();
        for (int c = 0; c < 128; c++) {
            float wv = ws[tx * 132 + c];
#pragma unroll
            for (int i = 0; i < 4; i++)
                acc[i] += xs[(ty * 4 + i) * 132 + c] * wv;
        }
        __syncthreads();
    }
    float bq = qkv_b[n0 + tx];
#pragma unroll
    for (int i = 0; i < 4; i++)
        g_qc[(size_t)(ty * 4 + i) * CT + n0 + tx] = acc[i] + bq;
}

__global__ __launch_bounds__(256) void cls_wt(
    const float* __restrict__ qkv_w, const float* __restrict__ qkv_b)
{
    __shared__ float qs[64 * 68];
    __shared__ float wks[64 * 68];
    const int tid = threadIdx.x;
    const int c0 = blockIdx.x * 64;
    const int h = blockIdx.y;
    const int tx = tid & 31;
    const int ty = tid >> 5;

#pragma unroll
    for (int it = 0; it < 4; it++) {
        int g = tid + it * 256;
        int row = g >> 4, d4 = (g & 15) * 4;
        *(float4*)(qs + row * 68 + d4) =
            *(const float4*)(g_qc + (size_t)row * CT + h * 64 + d4);
    }
#pragma unroll
    for (int it = 0; it < 4; it++) {
        int g = tid + it * 256;
        int d = g >> 4, c4 = (g & 15) * 4;
        *(float4*)(wks + d * 68 + c4) =
            *(const float4*)(qkv_w + (size_t)(CT + h * 64 + d) * CT + c0 + c4);
    }
    __syncthreads();

    float acc[8][2];
#pragma unroll
    for (int i = 0; i < 8; i++) { acc[i][0] = 0.f; acc[i][1] = 0.f; }
    for (int d = 0; d < 64; d++) {
        float w0 = wks[d * 68 + tx * 2];
        float w1 = wks[d * 68 + tx * 2 + 1];
#pragma unroll
        for (int i = 0; i < 8; i++) {
            float qv = qs[(ty * 8 + i) * 68 + d];
            acc[i][0] += qv * w0;
            acc[i][1] += qv * w1;
        }
    }
#pragma unroll
    for (int i = 0; i < 8; i++) {
        int b = ty * 8 + i;
        g_wt[(size_t)(b * HT + h) * CT + c0 + tx * 2]     = acc[i][0];
        g_wt[(size_t)(b * HT + h) * CT + c0 + tx * 2 + 1] = acc[i][1];
    }

    if (blockIdx.x == 0 && tid < 64) {
        float s = 0.f;
        for (int d = 0; d < 64; d++)
            s += qs[tid * 68 + d] * qkv_b[CT + h * 64 + d];
        g_beta[tid * HT + h] = s;
    }
}

__global__ __launch_bounds__(256) void cls_fused(
    const float* __restrict__ x, float* __restrict__ out_cls)
{
    __shared__ float wts[HT * CT];
    __shared__ float S[HT * 200];
    __shared__ float betas[HT];
    const int b = blockIdx.x;
    const int tid = threadIdx.x, lane = tid & 31, w = tid >> 5;

    for (int i = tid; i < HT * CT / 4; i += 256)
        ((float4*)wts)[i] = ((const float4*)(g_wt + (size_t)b * HT * CT))[i];
    if (tid < HT) betas[tid] = g_beta[b * HT + tid];
    __syncthreads();

    const int jstart = w * 25;
    const int jend = (jstart + 25 < NT) ? jstart + 25 : NT;
    const float* xb = x + (size_t)b * NT * CT;

    for (int jb = jstart; jb < jend; jb += 4) {
        const int nj = (jend - jb < 4) ? (jend - jb) : 4;
        float acc[HT][4];
#pragma unroll
        for (int h = 0; h < HT; h++)
#pragma unroll
            for (int jj = 0; jj < 4; jj++) acc[h][jj] = 0.f;

        int jr[4];
#pragma unroll
        for (int jj = 0; jj < 4; jj++) {
            int j = jb + jj; if (j > NT - 1) j = NT - 1;
            jr[jj] = j;
        }
#pragma unroll 4
        for (int t = 0; t < 24; t++) {
            const int c = lane + 32 * t;
            float xv[4];
#pragma unroll
            for (int jj = 0; jj < 4; jj++) xv[jj] = xb[(size_t)jr[jj] * CT + c];
#pragma unroll
            for (int h = 0; h < HT; h++) {
                float wv = wts[h * CT + c];
#pragma unroll
                for (int jj = 0; jj < 4; jj++) acc[h][jj] += wv * xv[jj];
            }
        }
#pragma unroll
        for (int h = 0; h < HT; h++)
#pragma unroll
            for (int jj = 0; jj < 4; jj++) {
                float s = acc[h][jj];
#pragma unroll
                for (int o = 16; o; o >>= 1) s += __shfl_xor_sync(~0u, s, o);
                if (lane == 0 && jj < nj)
                    S[h * 200 + jb + jj] = (s + betas[h]) * 0.125f;
            }
    }
    __syncthreads();

    for (int hh = w; hh < HT; hh += 8) {
        float vx[7];
        float mx = -FLT_MAX;
#pragma unroll
        for (int t = 0; t < 7; t++) {
            int j = lane + 32 * t;
            vx[t] = (j < NT) ? S[hh * 200 + j] : -FLT_MAX;
            mx = fmaxf(mx, vx[t]);
        }
#pragma unroll
        for (int o = 16; o; o >>= 1) mx = fmaxf(mx, __shfl_xor_sync(~0u, mx, o));
        float sum = 0.f;
#pragma unroll
        for (int t = 0; t < 7; t++) {
            int j = lane + 32 * t;
            float e = (j < NT) ? __expf(vx[t] - mx) : 0.f;
            vx[t] = e;
            sum += e;
        }
#pragma unroll
        for (int o = 16; o; o >>= 1) sum += __shfl_xor_sync(~0u, sum, o);
        float inv = 1.f / sum;
#pragma unroll
        for (int t = 0; t < 7; t++) {
            int j = lane + 32 * t;
            if (j < NT) S[hh * 200 + j] = vx[t] * inv;
        }
    }
    __syncthreads();

    for (int j = 1 + tid; j < NT; j += 256) {
        float s = 0.f;
#pragma unroll
        for (int h = 0; h < HT; h++) s += S[h * 200 + j];
        out_cls[b * (NT - 1) + (j - 1)] = s * (1.f / 12.f);
    }
}

// ---------------------------------------------------------------------------
// Top-k per batch + index broadcast
// ---------------------------------------------------------------------------
__global__ __launch_bounds__(256) void topk_kernel(
    const float* __restrict__ cls, float* __restrict__ out_idx,
    float* __restrict__ out_index)
{
    __shared__ float v[256];
    __shared__ int   id[256];
    const int bb = blockIdx.x;
    const int t = threadIdx.x;

    v[t]  = (t < NT - 1) ? cls[bb * (NT - 1) + t] : -FLT_MAX;
    id[t] = t;
    __syncthreads();

    for (int ksz = 2; ksz <= 256; ksz <<= 1) {
        for (int j = ksz >> 1; j > 0; j >>= 1) {
            int ixj = t ^ j;
            if (ixj > t) {
                float v1 = v[t], v2 = v[ixj];
                int i1 = id[t], i2 = id[ixj];
                bool before = (v1 > v2) || (v1 == v2 && i1 < i2);
                bool desc = ((t & ksz) == 0);
                if (desc ? !before : before) {
                    v[t] = v2; v[ixj] = v1;
                    id[t] = i2; id[ixj] = i1;
                }
            }
            __syncthreads();
        }
    }

    if (t < LEFT) out_idx[bb * LEFT + t] = (float)id[t];
    float* dst = out_index + (size_t)bb * LEFT * CT;
    for (int e = t; e < LEFT * CT; e += 256) dst[e] = (float)id[e / CT];
}

// ---------------------------------------------------------------------------
extern "C" void kernel_launch(void* const* d_in, const int* in_sizes, int n_in,
                              void* d_out, int out_size)
{
    const float* x      = (const float*)d_in[0];
    const float* qkv_w  = (const float*)d_in[1];
    const float* qkv_b  = (const float*)d_in[2];
    const float* proj_w = (const float*)d_in[3];
    const float* proj_b = (const float*)d_in[4];

    float* out_o     = (float*)d_out;
    float* out_index = out_o     + (size_t)BB * NT * CT;
    float* out_idx   = out_index + (size_t)BB * LEFT * CT;
    float* out_cls   = out_idx   + (size_t)BB * LEFT;

    float *ao_ptr, *xr_ptr, *wqr_ptr, *wpr_ptr;
    cudaGetSymbolAddress((void**)&ao_ptr,  g_ao);
    cudaGetSymbolAddress((void**)&xr_ptr,  g_xr);
    cudaGetSymbolAddress((void**)&wqr_ptr, g_wqr);
    cudaGetSymbolAddress((void**)&wpr_ptr, g_wpr);

    cudaFuncSetAttribute(gemm_mma, cudaFuncAttributeMaxDynamicSharedMemorySize, GEMM_SMEM);
    cudaFuncSetAttribute(attn_mma, cudaFuncAttributeMaxDynamicSharedMemorySize, ATT_SMEM);

    const int mby = (MROWS + 127) / 128;   // 99

    // 1-3) prepass rounds
    {
        int n4 = MROWS * CT / 4;
        round_tf32_kernel<<<(n4 + 255) / 256, 256>>>(x, xr_ptr, n4);
        n4 = 3 * CT * CT / 4;
        round_tf32_kernel<<<(n4 + 255) / 256, 256>>>(qkv_w, wqr_ptr, n4);
        n4 = CT * CT / 4;
        round_tf32_kernel<<<(n4 + 255) / 256, 256>>>(proj_w, wpr_ptr, n4);
    }

    // 4) qkv projection (R12 proven 128x256)
    gemm_mma<<<dim3(3 * CT / 256, mby), 512, GEMM_SMEM>>>(
        xr_ptr, wqr_ptr, qkv_b, MROWS, 3 * CT, CT, 0, nullptr);

    // 5) fused attention (QTILE=128)
    attn_mma<<<BB * HT * 2, 512, ATT_SMEM>>>();

    // 6-8) exact cls path (dense)
    cls_qcls<<<CT / 16, 256>>>(x, qkv_w, qkv_b);
    cls_wt<<<dim3(12, HT), 256>>>(qkv_w, qkv_b);
    cls_fused<<<BB, 256>>>(x, out_cls);

    // 9) output projection
    gemm_mma<<<dim3(CT / 256, mby), 512, GEMM_SMEM>>>(
        ao_ptr, wpr_ptr, proj_b, MROWS, CT, CT, 1, out_o);

    // 10) top-k + index broadcast
    topk_kernel<<<BB, 256>>>(out_cls, out_idx, out_index);
}

// round 16
// speedup vs baseline: 1.1368x; 1.0651x over previous
#include <cuda_runtime.h>
#include <cuda_bf16.h>
#include <cstdint>
#include <float.h>
#include <math.h>

#define BB   64
#define NT   197
#define CT   768
#define HT   12
#define DT   64
#define LEFT 137
#define MROWS (BB*NT)     // 12608

// device scratch
__device__ uint32_t g_qh[BB*HT*NT*32];
__device__ uint32_t g_ql[BB*HT*NT*32];
__device__ uint32_t g_kh[BB*HT*NT*32];
__device__ uint32_t g_kl[BB*HT*NT*32];
__device__ float    g_v [BB*HT*NT*DT];
__device__ float    g_ao[BB*NT*CT];
__device__ float    g_wt[BB*HT*CT];
__device__ float    g_beta[BB*HT];
__device__ float    g_qc[BB*CT];
__device__ float    g_xr[MROWS*CT];
__device__ float    g_wqr[3*CT*CT];
__device__ float    g_wpr[CT*CT];

// ---------------------------------------------------------------------------
// helpers
// ---------------------------------------------------------------------------
__device__ __forceinline__ uint32_t smem_u32(const void* p) {
    uint32_t a;
    asm("{ .reg .u64 t; cvta.to.shared.u64 t, %1; cvt.u32.u64 %0, t; }" : "=r"(a) : "l"(p));
    return a;
}
__device__ __forceinline__ void cp16(uint32_t saddr, const void* g) {
    asm volatile("cp.async.ca.shared.global [%0], [%1], 16;" :: "r"(saddr), "l"(g));
}
__device__ __forceinline__ void cp_commit() {
    asm volatile("cp.async.commit_group;" ::: "memory");
}
__device__ __forceinline__ void cp_wait1() {
    asm volatile("cp.async.wait_group 1;" ::: "memory");
}
__device__ __forceinline__ void cp_wait0() {
    asm volatile("cp.async.wait_group 0;" ::: "memory");
}
__device__ __forceinline__ uint32_t f2tf32(float v) {
    uint32_t r;
    asm("cvt.rna.tf32.f32 %0, %1;" : "=r"(r) : "f"(v));
    return r;
}
__device__ __forceinline__ float roundtf(float v) {
    return __uint_as_float(f2tf32(v));
}
__device__ __forceinline__ uint32_t packbf(float x, float y) {
    __nv_bfloat162 t = __floats2bfloat162_rn(x, y);
    return *reinterpret_cast<uint32_t*>(&t);
}
__device__ __forceinline__ void bf16split(float x, float y, uint32_t& hi, uint32_t& lo) {
    float xh = __bfloat162float(__float2bfloat16_rn(x));
    float yh = __bfloat162float(__float2bfloat16_rn(y));
    hi = packbf(xh, yh);
    lo = packbf(x - xh, y - yh);
}
__device__ __forceinline__ void ldsm4(uint32_t& r0, uint32_t& r1, uint32_t& r2,
                                      uint32_t& r3, uint32_t sa) {
    asm volatile("ldmatrix.sync.aligned.m8n8.x4.shared.b16 {%0,%1,%2,%3}, [%4];"
                 : "=r"(r0), "=r"(r1), "=r"(r2), "=r"(r3) : "r"(sa));
}
__device__ __forceinline__ void mma_tf32(float c[4], uint32_t a0, uint32_t a1,
                                         uint32_t a2, uint32_t a3,
                                         uint32_t b0, uint32_t b1) {
    asm volatile(
        "mma.sync.aligned.m16n8k8.row.col.f32.tf32.tf32.f32 "
        "{%0,%1,%2,%3}, {%4,%5,%6,%7}, {%8,%9}, {%0,%1,%2,%3};"
        : "+f"(c[0]), "+f"(c[1]), "+f"(c[2]), "+f"(c[3])
        : "r"(a0), "r"(a1), "r"(a2), "r"(a3), "r"(b0), "r"(b1));
}
__device__ __forceinline__ void mma_bf16(float c[4], uint32_t a0, uint32_t a1,
                                         uint32_t a2, uint32_t a3,
                                         uint32_t b0, uint32_t b1) {
    asm volatile(
        "mma.sync.aligned.m16n8k16.row.col.f32.bf16.bf16.f32 "
        "{%0,%1,%2,%3}, {%4,%5,%6,%7}, {%8,%9}, {%0,%1,%2,%3};"
        : "+f"(c[0]), "+f"(c[1]), "+f"(c[2]), "+f"(c[3])
        : "r"(a0), "r"(a1), "r"(a2), "r"(a3), "r"(b0), "r"(b1));
}

// ---------------------------------------------------------------------------
// Prepass: round float array to tf32
// ---------------------------------------------------------------------------
__global__ __launch_bounds__(256) void round_tf32_kernel(
    const float* __restrict__ src, float* __restrict__ dst, int n4)
{
    int i = blockIdx.x * blockDim.x + threadIdx.x;
    if (i < n4) {
        float4 v = ((const float4*)src)[i];
        v.x = roundtf(v.x); v.y = roundtf(v.y);
        v.z = roundtf(v.z); v.w = roundtf(v.w);
        ((float4*)dst)[i] = v;
    }
}

// ---------------------------------------------------------------------------
// tf32 mma.sync GEMM with ldmatrix fragments. (R12 proven — DO NOT TOUCH)
// Block 128x256, BK=32, 512 threads. 3-stage cp.async, wait<=1, one barrier.
// ---------------------------------------------------------------------------
#define RS    36
#define BUFA  (128*RS)
#define BUFB  (256*RS)
#define GEMM_SMEM ((3*BUFA + 3*BUFB)*4)

__global__ __launch_bounds__(512) void gemm_mma(
    const float* __restrict__ A, const float* __restrict__ Bw,
    const float* __restrict__ bias, int M, int N, int K, int mode,
    float* __restrict__ Cout)
{
    extern __shared__ float sm[];

    const int tid = threadIdx.x, lane = tid & 31, wid = tid >> 5;
    const int bm = blockIdx.y * 128, bn = blockIdx.x * 256;
    const int wm = (wid & 3) * 32, wn = (wid >> 2) * 64;
    const int gr = lane >> 2, lc = lane & 3;

    uint32_t sA[3], sB[3];
#pragma unroll
    for (int i = 0; i < 3; i++) {
        sA[i] = smem_u32(sm + i * BUFA);
        sB[i] = smem_u32(sm + 3 * BUFA + i * BUFB);
    }

    float c[2][8][4];
#pragma unroll
    for (int i = 0; i < 2; i++)
#pragma unroll
        for (int j = 0; j < 8; j++)
#pragma unroll
            for (int r = 0; r < 4; r++) c[i][j][r] = 0.f;

    const int row_l = tid >> 3;
    const int c4 = tid & 7;

    int gA[2], gB[4];
#pragma unroll
    for (int it = 0; it < 2; it++) {
        int ga = bm + row_l + it * 64; if (ga > M - 1) ga = M - 1;
        gA[it] = ga;
    }
#pragma unroll
    for (int it = 0; it < 4; it++) {
        int gb = bn + row_l + it * 64; if (gb > N - 1) gb = N - 1;
        gB[it] = gb;
    }
    const uint32_t soff = (uint32_t)(row_l * RS + c4 * 4) * 4;
    const uint32_t sstep = (uint32_t)(64 * RS) * 4;

    const int lmA_row = wm + (lane & 15);
    const int lmA_col = (lane >> 4) << 2;
    const int lmB_row = wn + (lane & 7) + ((lane >> 4) & 1) * 8;
    const int lmB_col = ((lane >> 3) & 1) * 4;

    const int S = K / 32;

#pragma unroll
    for (int ps = 0; ps < 2; ps++) {
        const int k0 = ps * 32;
#pragma unroll
        for (int it = 0; it < 2; it++)
            cp16(sA[ps] + soff + it * sstep, A  + (size_t)gA[it] * K + k0 + c4 * 4);
#pragma unroll
        for (int it = 0; it < 4; it++)
            cp16(sB[ps] + soff + it * sstep, Bw + (size_t)gB[it] * K + k0 + c4 * 4);
        cp_commit();
    }

    int cb = 0, lb = 2;
    for (int s = 0; s < S; s++) {
        cp_wait1();
        __syncthreads();

        const int ls = s + 2;
        if (ls < S) {
            const int k0 = ls * 32;
#pragma unroll
            for (int it = 0; it < 2; it++)
                cp16(sA[lb] + soff + it * sstep, A  + (size_t)gA[it] * K + k0 + c4 * 4);
#pragma unroll
            for (int it = 0; it < 4; it++)
                cp16(sB[lb] + soff + it * sstep, Bw + (size_t)gB[it] * K + k0 + c4 * 4);
        }
        cp_commit();

        const uint32_t Abase = sA[cb];
        const uint32_t Bbase = sB[cb];
#pragma unroll
        for (int kk = 0; kk < 4; kk++) {
            const int kbase = kk * 8;
            uint32_t af[2][4];
#pragma unroll
            for (int mt = 0; mt < 2; mt++)
                ldsm4(af[mt][0], af[mt][1], af[mt][2], af[mt][3],
                      Abase + (uint32_t)((lmA_row + mt * 16) * RS + kbase + lmA_col) * 4);
            uint32_t bf[8][2];
#pragma unroll
            for (int pr = 0; pr < 4; pr++)
                ldsm4(bf[2*pr][0], bf[2*pr][1], bf[2*pr+1][0], bf[2*pr+1][1],
                      Bbase + (uint32_t)((lmB_row + pr * 16) * RS + kbase + lmB_col) * 4);
#pragma unroll
            for (int mt = 0; mt < 2; mt++)
#pragma unroll
                for (int nt = 0; nt < 8; nt++)
                    mma_tf32(c[mt][nt], af[mt][0], af[mt][1], af[mt][2], af[mt][3],
                             bf[nt][0], bf[nt][1]);
        }
        cb = (cb + 1) % 3;
        lb = (lb + 1) % 3;
    }

#pragma unroll
    for (int mt = 0; mt < 2; mt++) {
        const int r0 = bm + wm + mt * 16 + gr;
        const int r1 = r0 + 8;
#pragma unroll
        for (int nt = 0; nt < 8; nt++) {
            const int nc = bn + wn + nt * 8 + lc * 2;
            float2 bv = *(const float2*)(bias + nc);
            float2 o0 = { c[mt][nt][0] + bv.x, c[mt][nt][1] + bv.y };
            float2 o1 = { c[mt][nt][2] + bv.x, c[mt][nt][3] + bv.y };
            if (mode == 0) {
                const int which = nc / CT;
                const int rem = nc % CT;
                const int h = rem / DT, d0 = rem % DT;
                const int wi = d0 >> 1;
#pragma unroll
                for (int rr = 0; rr < 2; rr++) {
                    const int m = rr ? r1 : r0;
                    if (m >= M) continue;
                    float2 o = rr ? o1 : o0;
                    const int b_ = m / NT, tok = m % NT;
                    const size_t base = ((size_t)(b_ * HT + h)) * NT + tok;
                    if (which == 0) {
                        uint32_t hi, lo;
                        bf16split(o.x * 0.125f, o.y * 0.125f, hi, lo);
                        g_qh[base * 32 + wi] = hi;
                        g_ql[base * 32 + wi] = lo;
                    } else if (which == 1) {
                        uint32_t hi, lo;
                        bf16split(o.x, o.y, hi, lo);
                        g_kh[base * 32 + wi] = hi;
                        g_kl[base * 32 + wi] = lo;
                    } else {
                        *(float2*)(g_v + base * DT + d0) =
                            make_float2(roundtf(o.x), roundtf(o.y));
                    }
                }
            } else {
                if (r0 < M) *(float2*)(Cout + (size_t)r0 * N + nc) = o0;
                if (r1 < M) *(float2*)(Cout + (size_t)r1 * N + nc) = o1;
            }
        }
    }
}

// ---------------------------------------------------------------------------
// Fused attention, QTILE=128 (R15 proven)
// ---------------------------------------------------------------------------
#define RSQW 36
#define SVR  72
#define SSP  228
#define QTL  128
#define OFF_QH 0
#define OFF_QL (QTL*RSQW)
#define OFF_KH (2*QTL*RSQW)
#define OFF_KL (2*QTL*RSQW + 224*RSQW)
#define OFF_SS OFF_KH
#define OFF_VS (OFF_SS + QTL*SSP)
#define ATT_FLOATS (OFF_VS + 200*SVR)
#define ATT_SMEM (ATT_FLOATS*4)

__global__ __launch_bounds__(512) void attn_mma()
{
    extern __shared__ float smf[];
    const uint32_t sb = smem_u32(smf);

    const int tid = threadIdx.x, lane = tid & 31, wid = tid >> 5;
    const int gr = lane >> 2, lc = lane & 3;
    const int blk = blockIdx.x;
    const int bh = blk >> 1, qt = blk & 1;
    const int qbase = qt * QTL;
    const int b = bh / HT, h = bh % HT;
    const int rows_valid = (NT - qbase < QTL) ? (NT - qbase) : QTL;

    const uint32_t* Gqh = g_qh + (size_t)bh * NT * 32;
    const uint32_t* Gql = g_ql + (size_t)bh * NT * 32;
    const uint32_t* Gkh = g_kh + (size_t)bh * NT * 32;
    const uint32_t* Gkl = g_kl + (size_t)bh * NT * 32;
    const float*    Gv  = g_v  + (size_t)bh * NT * DT;

    for (int i = tid; i < QTL * 8; i += 512) {
        int r = i >> 3, w4 = (i & 7) * 4;
        int src = qbase + r; if (src > NT - 1) src = NT - 1;
        cp16(sb + (OFF_QH + r * RSQW + w4) * 4, Gqh + (size_t)src * 32 + w4);
        cp16(sb + (OFF_QL + r * RSQW + w4) * 4, Gql + (size_t)src * 32 + w4);
    }
    for (int i = tid; i < 224 * 8; i += 512) {
        int r = i >> 3, w4 = (i & 7) * 4;
        if (r < NT) {
            cp16(sb + (OFF_KH + r * RSQW + w4) * 4, Gkh + (size_t)r * 32 + w4);
            cp16(sb + (OFF_KL + r * RSQW + w4) * 4, Gkl + (size_t)r * 32 + w4);
        } else {
            *(float4*)(smf + OFF_KH + r * RSQW + w4) = make_float4(0.f,0.f,0.f,0.f);
            *(float4*)(smf + OFF_KL + r * RSQW + w4) = make_float4(0.f,0.f,0.f,0.f);
        }
    }
    for (int i = tid; i < 200 * 16; i += 512) {
        int r = i >> 4, c4 = (i & 15) * 4;
        if (r < NT) cp16(sb + (OFF_VS + r * SVR + c4) * 4, Gv + (size_t)r * DT + c4);
        else *(float4*)(smf + OFF_VS + r * SVR + c4) = make_float4(0.f,0.f,0.f,0.f);
    }
    cp_commit();
    cp_wait0();
    __syncthreads();

    const int wm = (wid & 7) * 16;
    const int wn = (wid >> 3) * 112;

    const int lmA_row = wm + (lane & 15);
    const int lmA_col = (lane >> 4) << 2;
    const int lmB_row = wn + (lane & 7) + ((lane >> 4) & 1) * 8;
    const int lmB_col = ((lane >> 3) & 1) * 4;

    const uint32_t sQH = sb + OFF_QH * 4;
    const uint32_t sQL = sb + OFF_QL * 4;
    const uint32_t sKH = sb + OFF_KH * 4;
    const uint32_t sKL = sb + OFF_KL * 4;

    float cS[14][4];
#pragma unroll
    for (int nt = 0; nt < 14; nt++)
#pragma unroll
        for (int r = 0; r < 4; r++) cS[nt][r] = 0.f;

#pragma unroll
    for (int kk = 0; kk < 4; kk++) {
        const int kbw = kk * 8;
        uint32_t ah[4], al[4];
        ldsm4(ah[0], ah[1], ah[2], ah[3],
              sQH + (uint32_t)(lmA_row * RSQW + kbw + lmA_col) * 4);
        ldsm4(al[0], al[1], al[2], al[3],
              sQL + (uint32_t)(lmA_row * RSQW + kbw + lmA_col) * 4);

#pragma unroll
        for (int pr = 0; pr < 7; pr++) {
            uint32_t bh0, bh1, bh2, bh3, bl0, bl1, bl2, bl3;
            ldsm4(bh0, bh1, bh2, bh3,
                  sKH + (uint32_t)((lmB_row + pr * 16) * RSQW + kbw + lmB_col) * 4);
            ldsm4(bl0, bl1, bl2, bl3,
                  sKL + (uint32_t)((lmB_row + pr * 16) * RSQW + kbw + lmB_col) * 4);
            mma_bf16(cS[2*pr],   ah[0], ah[1], ah[2], ah[3], bh0, bh1);
            mma_bf16(cS[2*pr],   ah[0], ah[1], ah[2], ah[3], bl0, bl1);
            mma_bf16(cS[2*pr],   al[0], al[1], al[2], al[3], bh0, bh1);
            mma_bf16(cS[2*pr+1], ah[0], ah[1], ah[2], ah[3], bh2, bh3);
            mma_bf16(cS[2*pr+1], ah[0], ah[1], ah[2], ah[3], bl2, bl3);
            mma_bf16(cS[2*pr+1], al[0], al[1], al[2], al[3], bh2, bh3);
        }
    }
    __syncthreads();

    float* Ss = smf + OFF_SS;
    {
        const int row = wm + gr;
#pragma unroll
        for (int nt = 0; nt < 14; nt++) {
            const int col = wn + nt * 8 + 2 * lc;
            *(float2*)(Ss + row * SSP + col)       = make_float2(cS[nt][0], cS[nt][1]);
            *(float2*)(Ss + (row + 8) * SSP + col) = make_float2(cS[nt][2], cS[nt][3]);
        }
    }
    __syncthreads();

    for (int r8 = 0; r8 < 8; r8++) {
        const int r = wid * 8 + r8;
        float vx[7];
        float mx = -FLT_MAX;
#pragma unroll
        for (int t = 0; t < 7; t++) {
            int j = lane + 32 * t;
            vx[t] = (j < NT) ? Ss[r * SSP + j] : -FLT_MAX;
            mx = fmaxf(mx, vx[t]);
        }
#pragma unroll
        for (int o = 16; o; o >>= 1) mx = fmaxf(mx, __shfl_xor_sync(~0u, mx, o));
        float sum = 0.f;
#pragma unroll
        for (int t = 0; t < 7; t++) {
            int j = lane + 32 * t;
            float e = (j < NT) ? __expf(vx[t] - mx) : 0.f;
            vx[t] = e;
            sum += e;
        }
#pragma unroll
        for (int o = 16; o; o >>= 1) sum += __shfl_xor_sync(~0u, sum, o);
        float inv = 1.f / sum;
#pragma unroll
        for (int t = 0; t < 7; t++) {
            int j = lane + 32 * t;
            if (j < NT)        Ss[r * SSP + j] = roundtf(vx[t] * inv);
            else if (j < 200)  Ss[r * SSP + j] = 0.f;
        }
    }
    __syncthreads();

    const float* Vs = smf + OFF_VS;
    const int wn2 = (wid >> 3) * 32;
    float cO[4][4];
#pragma unroll
    for (int nt = 0; nt < 4; nt++)
#pragma unroll
        for (int r = 0; r < 4; r++) cO[nt][r] = 0.f;

#pragma unroll
    for (int kk = 0; kk < 25; kk++) {
        const int kb = kk * 8;
        uint32_t af[4];
        {
            const uint32_t* p0 = (const uint32_t*)(Ss + (wm + gr) * SSP + kb + lc);
            af[0] = p0[0]; af[1] = p0[8 * SSP]; af[2] = p0[4]; af[3] = p0[8 * SSP + 4];
        }
        uint32_t bf[4][2];
#pragma unroll
        for (int nt = 0; nt < 4; nt++) {
            const uint32_t* p = (const uint32_t*)(Vs + (size_t)(kb + lc) * SVR + wn2 + nt * 8 + gr);
            bf[nt][0] = p[0];
            bf[nt][1] = p[4 * SVR];
        }
#pragma unroll
        for (int nt = 0; nt < 4; nt++)
            mma_tf32(cO[nt], af[0], af[1], af[2], af[3], bf[nt][0], bf[nt][1]);
    }
    {
        const int lr0 = wm + gr;
        const int lr1 = lr0 + 8;
#pragma unroll
        for (int nt = 0; nt < 4; nt++) {
            const int d = wn2 + nt * 8 + 2 * lc;
            if (lr0 < rows_valid)
                *(float2*)(g_ao + ((size_t)(b * NT + qbase + lr0)) * CT + h * DT + d)
                    = make_float2(roundtf(cO[nt][0]), roundtf(cO[nt][1]));
            if (lr1 < rows_valid)
                *(float2*)(g_ao + ((size_t)(b * NT + qbase + lr1)) * CT + h * DT + d)
                    = make_float2(roundtf(cO[nt][2]), roundtf(cO[nt][3]));
        }
    }
}

// ---------------------------------------------------------------------------
// Exact fp32 cls path — dense kernels (proven)
// ---------------------------------------------------------------------------
__global__ __launch_bounds__(256) void cls_qcls(
    const float* __restrict__ x, const float* __restrict__ qkv_w,
    const float* __restrict__ qkv_b)
{
    __shared__ float xs[64 * 132];
    __shared__ float ws[16 * 132];
    const int tid = threadIdx.x;
    const int n0 = blockIdx.x * 16;
    const int tx = tid & 15;
    const int ty = tid >> 4;

    float acc[4] = {0.f, 0.f, 0.f, 0.f};

    for (int c0 = 0; c0 < CT; c0 += 128) {
#pragma unroll
        for (int it = 0; it < 8; it++) {
            int g = tid + it * 256;
            int row = g >> 5, c4 = (g & 31) * 4;
            *(float4*)(xs + row * 132 + c4) =
                *(const float4*)(x + (size_t)row * NT * CT + c0 + c4);
        }
#pragma unroll
        for (int it = 0; it < 2; it++) {
            int g = tid + it * 256;
            if (g < 512) {
                int row = g >> 5, c4 = (g & 31) * 4;
                *(float4*)(ws + row * 132 + c4) =
                    *(const float4*)(qkv_w + (size_t)(n0 + row) * CT + c0 + c4);
            }
        }
        __syncthreads();
        for (int c = 0; c < 128; c++) {
            float wv = ws[tx * 132 + c];
#pragma unroll
            for (int i = 0; i < 4; i++)
                acc[i] += xs[(ty * 4 + i) * 132 + c] * wv;
        }
        __syncthreads();
    }
    float bq = qkv_b[n0 + tx];
#pragma unroll
    for (int i = 0; i < 4; i++)
        g_qc[(size_t)(ty * 4 + i) * CT + n0 + tx] = acc[i] + bq;
}

__global__ __launch_bounds__(256) void cls_wt(
    const float* __restrict__ qkv_w, const float* __restrict__ qkv_b)
{
    __shared__ float qs[64 * 68];
    __shared__ float wks[64 * 68];
    const int tid = threadIdx.x;
    const int c0 = blockIdx.x * 64;
    const int h = blockIdx.y;
    const int tx = tid & 31;
    const int ty = tid >> 5;

#pragma unroll
    for (int it = 0; it < 4; it++) {
        int g = tid + it * 256;
        int row = g >> 4, d4 = (g & 15) * 4;
        *(float4*)(qs + row * 68 + d4) =
            *(const float4*)(g_qc + (size_t)row * CT + h * 64 + d4);
    }
#pragma unroll
    for (int it = 0; it < 4; it++) {
        int g = tid + it * 256;
        int d = g >> 4, c4 = (g & 15) * 4;
        *(float4*)(wks + d * 68 + c4) =
            *(const float4*)(qkv_w + (size_t)(CT + h * 64 + d) * CT + c0 + c4);
    }
    __syncthreads();

    float acc[8][2];
#pragma unroll
    for (int i = 0; i < 8; i++) { acc[i][0] = 0.f; acc[i][1] = 0.f; }
    for (int d = 0; d < 64; d++) {
        float w0 = wks[d * 68 + tx * 2];
        float w1 = wks[d * 68 + tx * 2 + 1];
#pragma unroll
        for (int i = 0; i < 8; i++) {
            float qv = qs[(ty * 8 + i) * 68 + d];
            acc[i][0] += qv * w0;
            acc[i][1] += qv * w1;
        }
    }
#pragma unroll
    for (int i = 0; i < 8; i++) {
        int b = ty * 8 + i;
        g_wt[(size_t)(b * HT + h) * CT + c0 + tx * 2]     = acc[i][0];
        g_wt[(size_t)(b * HT + h) * CT + c0 + tx * 2 + 1] = acc[i][1];
    }

    if (blockIdx.x == 0 && tid < 64) {
        float s = 0.f;
        for (int d = 0; d < 64; d++)
            s += qs[tid * 68 + d] * qkv_b[CT + h * 64 + d];
        g_beta[tid * HT + h] = s;
    }
}

__global__ __launch_bounds__(256) void cls_fused(
    const float* __restrict__ x, float* __restrict__ out_cls)
{
    __shared__ float wts[HT * CT];
    __shared__ float S[HT * 200];
    __shared__ float betas[HT];
    const int b = blockIdx.x;
    const int tid = threadIdx.x, lane = tid & 31, w = tid >> 5;

    for (int i = tid; i < HT * CT / 4; i += 256)
        ((float4*)wts)[i] = ((const float4*)(g_wt + (size_t)b * HT * CT))[i];
    if (tid < HT) betas[tid] = g_beta[b * HT + tid];
    __syncthreads();

    const int jstart = w * 25;
    const int jend = (jstart + 25 < NT) ? jstart + 25 : NT;
    const float* xb = x + (size_t)b * NT * CT;

    for (int jb = jstart; jb < jend; jb += 4) {
        const int nj = (jend - jb < 4) ? (jend - jb) : 4;
        float acc[HT][4];
#pragma unroll
        for (int h = 0; h < HT; h++)
#pragma unroll
            for (int jj = 0; jj < 4; jj++) acc[h][jj] = 0.f;

        int jr[4];
#pragma unroll
        for (int jj = 0; jj < 4; jj++) {
            int j = jb + jj; if (j > NT - 1) j = NT - 1;
            jr[jj] = j;
        }
#pragma unroll 4
        for (int t = 0; t < 24; t++) {
            const int c = lane + 32 * t;
            float xv[4];
#pragma unroll
            for (int jj = 0; jj < 4; jj++) xv[jj] = xb[(size_t)jr[jj] * CT + c];
#pragma unroll
            for (int h = 0; h < HT; h++) {
                float wv = wts[h * CT + c];
#pragma unroll
                for (int jj = 0; jj < 4; jj++) acc[h][jj] += wv * xv[jj];
            }
        }
#pragma unroll
        for (int h = 0; h < HT; h++)
#pragma unroll
            for (int jj = 0; jj < 4; jj++) {
                float s = acc[h][jj];
#pragma unroll
                for (int o = 16; o; o >>= 1) s += __shfl_xor_sync(~0u, s, o);
                if (lane == 0 && jj < nj)
                    S[h * 200 + jb + jj] = (s + betas[h]) * 0.125f;
            }
    }
    __syncthreads();

    for (int hh = w; hh < HT; hh += 8) {
        float vx[7];
        float mx = -FLT_MAX;
#pragma unroll
        for (int t = 0; t < 7; t++) {
            int j = lane + 32 * t;
            vx[t] = (j < NT) ? S[hh * 200 + j] : -FLT_MAX;
            mx = fmaxf(mx, vx[t]);
        }
#pragma unroll
        for (int o = 16; o; o >>= 1) mx = fmaxf(mx, __shfl_xor_sync(~0u, mx, o));
        float sum = 0.f;
#pragma unroll
        for (int t = 0; t < 7; t++) {
            int j = lane + 32 * t;
            float e = (j < NT) ? __expf(vx[t] - mx) : 0.f;
            vx[t] = e;
            sum += e;
        }
#pragma unroll
        for (int o = 16; o; o >>= 1) sum += __shfl_xor_sync(~0u, sum, o);
        float inv = 1.f / sum;
#pragma unroll
        for (int t = 0; t < 7; t++) {
            int j = lane + 32 * t;
            if (j < NT) S[hh * 200 + j] = vx[t] * inv;
        }
    }
    __syncthreads();

    for (int j = 1 + tid; j < NT; j += 256) {
        float s = 0.f;
#pragma unroll
        for (int h = 0; h < HT; h++) s += S[h * 200 + j];
        out_cls[b * (NT - 1) + (j - 1)] = s * (1.f / 12.f);
    }
}

// ---------------------------------------------------------------------------
// Top-k per batch + index broadcast
// ---------------------------------------------------------------------------
__global__ __launch_bounds__(256) void topk_kernel(
    const float* __restrict__ cls, float* __restrict__ out_idx,
    float* __restrict__ out_index)
{
    __shared__ float v[256];
    __shared__ int   id[256];
    const int bb = blockIdx.x;
    const int t = threadIdx.x;

    v[t]  = (t < NT - 1) ? cls[bb * (NT - 1) + t] : -FLT_MAX;
    id[t] = t;
    __syncthreads();

    for (int ksz = 2; ksz <= 256; ksz <<= 1) {
        for (int j = ksz >> 1; j > 0; j >>= 1) {
            int ixj = t ^ j;
            if (ixj > t) {
                float v1 = v[t], v2 = v[ixj];
                int i1 = id[t], i2 = id[ixj];
                bool before = (v1 > v2) || (v1 == v2 && i1 < i2);
                bool desc = ((t & ksz) == 0);
                if (desc ? !before : before) {
                    v[t] = v2; v[ixj] = v1;
                    id[t] = i2; id[ixj] = i1;
                }
            }
            __syncthreads();
        }
    }

    if (t < LEFT) out_idx[bb * LEFT + t] = (float)id[t];
    float* dst = out_index + (size_t)bb * LEFT * CT;
    for (int e = t; e < LEFT * CT; e += 256) dst[e] = (float)id[e / CT];
}

// ---------------------------------------------------------------------------
extern "C" void kernel_launch(void* const* d_in, const int* in_sizes, int n_in,
                              void* d_out, int out_size)
{
    const float* x      = (const float*)d_in[0];
    const float* qkv_w  = (const float*)d_in[1];
    const float* qkv_b  = (const float*)d_in[2];
    const float* proj_w = (const float*)d_in[3];
    const float* proj_b = (const float*)d_in[4];

    float* out_o     = (float*)d_out;
    float* out_index = out_o     + (size_t)BB * NT * CT;
    float* out_idx   = out_index + (size_t)BB * LEFT * CT;
    float* out_cls   = out_idx   + (size_t)BB * LEFT;

    float *ao_ptr, *xr_ptr, *wqr_ptr, *wpr_ptr;
    cudaGetSymbolAddress((void**)&ao_ptr,  g_ao);
    cudaGetSymbolAddress((void**)&xr_ptr,  g_xr);
    cudaGetSymbolAddress((void**)&wqr_ptr, g_wqr);
    cudaGetSymbolAddress((void**)&wpr_ptr, g_wpr);

    cudaFuncSetAttribute(gemm_mma, cudaFuncAttributeMaxDynamicSharedMemorySize, GEMM_SMEM);
    cudaFuncSetAttribute(attn_mma, cudaFuncAttributeMaxDynamicSharedMemorySize, ATT_SMEM);

    // side stream + fork/join events (created once, before any capture)
    static cudaStream_t s1 = nullptr;
    static cudaEvent_t ev_fork = nullptr, ev_join = nullptr;
    if (!s1) {
        cudaStreamCreateWithFlags(&s1, cudaStreamNonBlocking);
        cudaEventCreateWithFlags(&ev_fork, cudaEventDisableTiming);
        cudaEventCreateWithFlags(&ev_join, cudaEventDisableTiming);
    }

    const int mby = (MROWS + 127) / 128;   // 99

    // fork: independent cls chain + proj_w rounding onto s1
    cudaEventRecord(ev_fork, 0);
    cudaStreamWaitEvent(s1, ev_fork, 0);

    cls_qcls<<<CT / 16, 256, 0, s1>>>(x, qkv_w, qkv_b);
    cls_wt<<<dim3(12, HT), 256, 0, s1>>>(qkv_w, qkv_b);
    cls_fused<<<BB, 256, 0, s1>>>(x, out_cls);
    {
        int n4 = CT * CT / 4;
        round_tf32_kernel<<<(n4 + 255) / 256, 256, 0, s1>>>(proj_w, wpr_ptr, n4);
    }
    cudaEventRecord(ev_join, s1);

    // main stream: rounds -> qkv -> attention
    {
        int n4 = MROWS * CT / 4;
        round_tf32_kernel<<<(n4 + 255) / 256, 256>>>(x, xr_ptr, n4);
        n4 = 3 * CT * CT / 4;
        round_tf32_kernel<<<(n4 + 255) / 256, 256>>>(qkv_w, wqr_ptr, n4);
    }
    gemm_mma<<<dim3(3 * CT / 256, mby), 512, GEMM_SMEM>>>(
        xr_ptr, wqr_ptr, qkv_b, MROWS, 3 * CT, CT, 0, nullptr);
    attn_mma<<<BB * HT * 2, 512, ATT_SMEM>>>();

    // join before proj (needs wpr) and topk (needs out_cls)
    cudaStreamWaitEvent(0, ev_join, 0);

    gemm_mma<<<dim3(CT / 256, mby), 512, GEMM_SMEM>>>(
        ao_ptr, wpr_ptr, proj_b, MROWS, CT, CT, 1, out_o);

    topk_kernel<<<BB, 256>>>(out_cls, out_idx, out_index);
}